// round 1
// baseline (speedup 1.0000x reference)
#include <cuda_runtime.h>

// ---------------- problem constants (match reference generator) ----------------
#define E_      32768
#define N0_     (15 * E_)            // 491520 existing node rows
#define MROWS_  (8 * E_)             // 262144 MLP rows (P=8 parents x E events)
#define NE_OLD_ 1114112
#define NE_NEW_ 2097152
#define NE_TOT_ (NE_OLD_ + NE_NEW_)  // 3211264
#define NNODES_ (31 * E_)            // 1015808 output node rows

// output layout (flattened tuple, float32):
//   x_new (NNODES_ x 64) | edge_index_new (2 x NE_TOT_) | edge_attr_new (NE_TOT_) | event_new (NNODES_)
#define EI_OFF_ ((size_t)NNODES_ * 64)            // 65,011,712
#define EA_OFF_ (EI_OFF_ + 2ull * NE_TOT_)        // 71,434,240
#define EV_OFF_ (EA_OFF_ + (size_t)NE_TOT_)       // 74,645,504

// ---------------- fused 2-layer MLP: 262144 rows, 128 -> relu 256 -> 128 ----------------
// block: 256 threads, 128 rows. smem: As[128][128] (64KB, reused as W2 slice),
// W1s[128][64] (32KB), HsT[256][128] (128KB). total 229,376 B dynamic.
__global__ void __launch_bounds__(256, 1)
mlp_kernel(const float* __restrict__ x, const int* __restrict__ ev,
           const float* __restrict__ g,
           const float* __restrict__ W1, const float* __restrict__ b1,
           const float* __restrict__ W2, const float* __restrict__ b2,
           float* __restrict__ out)
{
    extern __shared__ float sm[];
    float* As  = sm;            // 16384 floats  [k][r], k<128, r<128
    float* W1s = sm + 16384;    //  8192 floats  [k][c], c<64
    float* HsT = sm + 24576;    // 32768 floats  [c][r], c<256, r<128
    float* W2s = sm;            // alias As: [k2][c], k2<256, c<64

    const int t  = threadIdx.x;
    const int m0 = blockIdx.x << 7;   // first MLP row of this block

    // ---- stage A: load input tile transposed: row m features = [x[7E+m], g[event]] ----
    {
        const int r = t >> 1, half = t & 1;
        const int m = m0 + r;
        const float* src;
        if (half == 0) {
            src = x + ((size_t)(7 * E_) + (size_t)m) * 64;
        } else {
            const int e = ev[7 * E_ + m];
            src = g + (size_t)e * 64;
        }
        #pragma unroll
        for (int i = 0; i < 16; i++) {
            float4 v = ((const float4*)src)[i];
            int k = half * 64 + i * 4;
            As[(k + 0) * 128 + r] = v.x;
            As[(k + 1) * 128 + r] = v.y;
            As[(k + 2) * 128 + r] = v.z;
            As[(k + 3) * 128 + r] = v.w;
        }
    }

    const int tm = t & 15;         // row micro-group: rows r0..r0+7
    const int tc = t >> 4;         // col micro-group: cols tc*4..tc*4+3
    const int r0 = tm << 3;

    // ---- stage B: hidden = relu(A @ W1 + b1), 4 column tiles of 64 ----
    #pragma unroll 1
    for (int tile = 0; tile < 4; tile++) {
        const int c0 = tile << 6;
        __syncthreads();                      // As ready (tile 0) / W1s reads done (tiles>0)
        #pragma unroll
        for (int it = 0; it < 8; it++) {
            int u = t + (it << 8);
            int k = u >> 4, cw = u & 15;
            ((float4*)(W1s + k * 64))[cw] = ((const float4*)(W1 + k * 256 + c0))[cw];
        }
        __syncthreads();

        float acc[8][4];
        #pragma unroll
        for (int i = 0; i < 8; i++)
            #pragma unroll
            for (int j = 0; j < 4; j++) acc[i][j] = 0.0f;

        #pragma unroll 4
        for (int k = 0; k < 128; k++) {
            float4 a0 = *(const float4*)(As + k * 128 + r0);
            float4 a1 = *(const float4*)(As + k * 128 + r0 + 4);
            float4 w  = *(const float4*)(W1s + k * 64 + (tc << 2));
            float aa[8] = {a0.x, a0.y, a0.z, a0.w, a1.x, a1.y, a1.z, a1.w};
            float ww[4] = {w.x, w.y, w.z, w.w};
            #pragma unroll
            for (int i = 0; i < 8; i++)
                #pragma unroll
                for (int j = 0; j < 4; j++)
                    acc[i][j] = fmaf(aa[i], ww[j], acc[i][j]);
        }

        float4 bb = *(const float4*)(b1 + c0 + (tc << 2));
        float bj[4] = {bb.x, bb.y, bb.z, bb.w};
        #pragma unroll
        for (int j = 0; j < 4; j++) {
            int c = c0 + (tc << 2) + j;
            #pragma unroll
            for (int i = 0; i < 8; i++)
                HsT[c * 128 + r0 + i] = fmaxf(acc[i][j] + bj[j], 0.0f);
        }
    }

    // ---- stage C: out = H @ W2 + b2, 2 column tiles of 64 (tile == branch) ----
    #pragma unroll 1
    for (int tile = 0; tile < 2; tile++) {
        const int c0 = tile << 6;
        __syncthreads();                      // HsT complete / As reads done / W2s reuse
        #pragma unroll
        for (int it = 0; it < 16; it++) {
            int u = t + (it << 8);
            int k = u >> 4, cw = u & 15;
            ((float4*)(W2s + k * 64))[cw] = ((const float4*)(W2 + k * 128 + c0))[cw];
        }
        __syncthreads();

        float acc[8][4];
        #pragma unroll
        for (int i = 0; i < 8; i++)
            #pragma unroll
            for (int j = 0; j < 4; j++) acc[i][j] = 0.0f;

        #pragma unroll 4
        for (int k = 0; k < 256; k++) {
            float4 h0 = *(const float4*)(HsT + k * 128 + r0);
            float4 h1 = *(const float4*)(HsT + k * 128 + r0 + 4);
            float4 w  = *(const float4*)(W2s + k * 64 + (tc << 2));
            float hh[8] = {h0.x, h0.y, h0.z, h0.w, h1.x, h1.y, h1.z, h1.w};
            float ww[4] = {w.x, w.y, w.z, w.w};
            #pragma unroll
            for (int i = 0; i < 8; i++)
                #pragma unroll
                for (int j = 0; j < 4; j++)
                    acc[i][j] = fmaf(hh[i], ww[j], acc[i][j]);
        }

        float4 bb = *(const float4*)(b2 + c0 + (tc << 2));
        #pragma unroll
        for (int i = 0; i < 8; i++) {
            int m = m0 + r0 + i;
            int e = m & (E_ - 1);
            int p = m >> 15;
            // x_new row = N0 + (p*E + e)*2 + branch, branch = tile; cols f = tc*4..tc*4+3
            size_t orow = (size_t)N0_ + ((size_t)p << 16) + 2u * (size_t)e + (size_t)tile;
            float4 v;
            v.x = acc[i][0] + bb.x;
            v.y = acc[i][1] + bb.y;
            v.z = acc[i][2] + bb.z;
            v.w = acc[i][3] + bb.w;
            *(float4*)(out + orow * 64 + (tc << 2)) = v;
        }
    }
}

// ---------------- edge / attr / event fills ----------------
__global__ void copy_old_edges_kernel(const int* __restrict__ ei,
                                      const int* __restrict__ ea,
                                      float* __restrict__ out)
{
    int i = blockIdx.x * blockDim.x + threadIdx.x;
    if (i < NE_OLD_) {
        out[EI_OFF_ + i]                      = (float)ei[i];               // src row
        out[EI_OFF_ + (size_t)NE_TOT_ + i]    = (float)ei[NE_OLD_ + i];     // tgt row
        out[EA_OFF_ + i]                      = (float)ea[i];
    }
}

__global__ void new_edges_kernel(float* __restrict__ out)
{
    int i = blockIdx.x * blockDim.x + threadIdx.x;
    if (i >= NE_NEW_) return;
    int p    = i >> 18;          // / (4 * 2E)
    int rem  = i & 262143;
    int dm1  = rem >> 16;        // degree - 1
    int j    = rem & 65535;      // within B*E
    int e    = j & (E_ - 1);
    int anc  = E_ * ((8 >> dm1) - 1);           // 7E, 3E, E, 0
    int src  = anc + (p >> dm1) * E_ + e;
    int tgt  = N0_ + (p << 16) + j;
    out[EI_OFF_ + NE_OLD_ + i]                   = (float)src;
    out[EI_OFF_ + (size_t)NE_TOT_ + NE_OLD_ + i] = (float)tgt;
    out[EA_OFF_ + NE_OLD_ + i]                   = (float)(dm1 + 1);
}

__global__ void event_kernel(const int* __restrict__ ev, float* __restrict__ out)
{
    int i = blockIdx.x * blockDim.x + threadIdx.x;
    if (i < NNODES_) {
        float v = (i < N0_) ? (float)ev[i] : (float)((i - N0_) & (E_ - 1));
        out[EV_OFF_ + i] = v;
    }
}

// ---------------- launch ----------------
extern "C" void kernel_launch(void* const* d_in, const int* in_sizes, int n_in,
                              void* d_out, int out_size)
{
    const float* x  = (const float*)d_in[0];
    const int*   ei = (const int*)  d_in[1];
    const int*   ea = (const int*)  d_in[2];
    const int*   ev = (const int*)  d_in[3];
    const float* g  = (const float*)d_in[4];
    const float* W1 = (const float*)d_in[5];
    const float* b1 = (const float*)d_in[6];
    const float* W2 = (const float*)d_in[7];
    const float* b2 = (const float*)d_in[8];
    float* out = (float*)d_out;

    // x prefix of x_new: straight fp32 copy (125.8 MB)
    cudaMemcpyAsync(out, x, (size_t)N0_ * 64 * sizeof(float),
                    cudaMemcpyDeviceToDevice);

    copy_old_edges_kernel<<<(NE_OLD_ + 255) / 256, 256>>>(ei, ea, out);
    new_edges_kernel<<<(NE_NEW_ + 255) / 256, 256>>>(out);
    event_kernel<<<(NNODES_ + 255) / 256, 256>>>(ev, out);

    static const int kSmem = 229376;   // 56K floats: As/W2s + W1s + HsT
    cudaFuncSetAttribute(mlp_kernel, cudaFuncAttributeMaxDynamicSharedMemorySize, kSmem);
    mlp_kernel<<<MROWS_ / 128, 256, kSmem>>>(x, ev, g, W1, b1, W2, b2, out);
}

// round 3
// speedup vs baseline: 2.6929x; 2.6929x over previous
#include <cuda_runtime.h>
#include <cuda_bf16.h>
#include <cstdint>

// ---------------- problem constants ----------------
#define E_      32768
#define N0_     (15 * E_)
#define MROWS_  (8 * E_)
#define NE_OLD_ 1114112
#define NE_NEW_ 2097152
#define NE_TOT_ (NE_OLD_ + NE_NEW_)
#define NNODES_ (31 * E_)

#define EI_OFF_ ((size_t)NNODES_ * 64)
#define EA_OFF_ (EI_OFF_ + 2ull * NE_TOT_)
#define EV_OFF_ (EA_OFF_ + (size_t)NE_TOT_)

// ---------------- smem layout (bytes) ----------------
#define TILE_B  34816                 // 128 rows x 272 B (136 bf16, padded)
#define SM_AH   0
#define SM_AL   (SM_AH + TILE_B)
#define SM_W1H  (SM_AL + TILE_B)
#define SM_W1L  (SM_W1H + TILE_B)
#define SM_W2H  (SM_W1L + TILE_B)
#define SM_W2L  (SM_W2H + TILE_B)
#define SM_SZ   (SM_W2L + TILE_B)     // 208896

// ---------------- PTX helpers (base ISA only) ----------------
__device__ __forceinline__ uint32_t smem_u32(const void* p) {
    uint32_t a;
    asm("{ .reg .u64 t; cvta.to.shared.u64 t, %1; cvt.u32.u64 %0, t; }" : "=r"(a) : "l"(p));
    return a;
}

#define CPA16(dst, src) asm volatile("cp.async.cg.shared.global [%0], [%1], 16;" :: "r"(dst), "l"(src) : "memory")
#define CPA_COMMIT()    asm volatile("cp.async.commit_group;" ::: "memory")
#define CPA_WAIT(n)     asm volatile("cp.async.wait_group %0;" :: "n"(n) : "memory")

#define LDSM4(r0, r1, r2, r3, a)                                                   \
    asm volatile("ldmatrix.sync.aligned.m8n8.x4.shared.b16 {%0,%1,%2,%3}, [%4];"   \
        : "=r"(r0), "=r"(r1), "=r"(r2), "=r"(r3) : "r"(a))

#define MMA_BF16(d, a0, a1, a2, a3, b0, b1)                                        \
    asm volatile("mma.sync.aligned.m16n8k16.row.col.f32.bf16.bf16.f32 "            \
        "{%0,%1,%2,%3}, {%4,%5,%6,%7}, {%8,%9}, {%0,%1,%2,%3};"                    \
        : "+f"((d)[0]), "+f"((d)[1]), "+f"((d)[2]), "+f"((d)[3])                   \
        : "r"(a0), "r"(a1), "r"(a2), "r"(a3), "r"(b0), "r"(b1))

__device__ __forceinline__ uint32_t pack2(__nv_bfloat16 a, __nv_bfloat16 b) {
    return ((uint32_t)__bfloat16_as_ushort(b) << 16) | (uint32_t)__bfloat16_as_ushort(a);
}
__device__ __forceinline__ void split_bf16(float v, __nv_bfloat16& h, __nv_bfloat16& l) {
    h = __float2bfloat16(v);
    l = __float2bfloat16(v - __bfloat162float(h));
}

// ---------------- pre-padded weight images ----------------
__device__ __align__(16) unsigned char glW1h[2 * TILE_B];
__device__ __align__(16) unsigned char glW1l[2 * TILE_B];
__device__ __align__(16) unsigned char glW2h[2 * TILE_B];
__device__ __align__(16) unsigned char glW2l[2 * TILE_B];

__global__ void prep_w1_kernel(const float* __restrict__ W1) {
    int i = blockIdx.x * blockDim.x + threadIdx.x;
    if (i >= 256 * 128) return;
    int n = i >> 7, k = i & 127;
    __nv_bfloat16 h, l;
    split_bf16(W1[k * 256 + n], h, l);
    uint32_t off = (uint32_t)(n >> 7) * TILE_B + (uint32_t)(n & 127) * 272u + (uint32_t)k * 2u;
    *(__nv_bfloat16*)(glW1h + off) = h;
    *(__nv_bfloat16*)(glW1l + off) = l;
}
__global__ void prep_w2_kernel(const float* __restrict__ W2) {
    int i = blockIdx.x * blockDim.x + threadIdx.x;
    if (i >= 128 * 256) return;
    int n = i >> 8, k = i & 255;
    __nv_bfloat16 h, l;
    split_bf16(W2[k * 128 + n], h, l);
    uint32_t off = (uint32_t)(k >> 7) * TILE_B + (uint32_t)n * 272u + (uint32_t)(k & 127) * 2u;
    *(__nv_bfloat16*)(glW2h + off) = h;
    *(__nv_bfloat16*)(glW2l + off) = l;
}

__device__ __forceinline__ void cpa_tile(uint32_t dst, const unsigned char* src, int t) {
    #pragma unroll 3
    for (int i = t; i < 2176; i += 256)
        CPA16(dst + (uint32_t)i * 16, src + (size_t)i * 16);
}

// ---------------- fused MLP on mma.sync bf16 hi/lo ----------------
__global__ void __launch_bounds__(256, 1)
mlp_mma_kernel(const float* __restrict__ x, const int* __restrict__ ev,
               const float* __restrict__ g,
               const float* __restrict__ b1, const float* __restrict__ b2,
               float* __restrict__ out)
{
    extern __shared__ __align__(128) unsigned char sm[];
    const int t = threadIdx.x;
    const int wid = t >> 5, l = t & 31;
    const int m0cta = blockIdx.x << 7;

    const uint32_t sb = smem_u32(sm);

    // weight loads, half 0
    cpa_tile(sb + SM_W1H, glW1h, t);
    cpa_tile(sb + SM_W1L, glW1l, t);
    cpa_tile(sb + SM_W2H, glW2h, t);
    cpa_tile(sb + SM_W2L, glW2l, t);
    CPA_COMMIT();

    // build A tile (hi/lo bf16, padded rows)
    {
        const int r = t >> 1, half = t & 1;
        const int m = m0cta + r;
        const float4* src;
        if (half == 0) src = (const float4*)(x + ((size_t)(7 * E_) + (size_t)m) * 64);
        else {
            const int e = ev[7 * E_ + m];
            src = (const float4*)(g + (size_t)e * 64);
        }
        unsigned char* Ah = sm + SM_AH + (size_t)r * 272 + (size_t)half * 128;
        unsigned char* Al = sm + SM_AL + (size_t)r * 272 + (size_t)half * 128;
        #pragma unroll
        for (int i = 0; i < 16; i++) {
            float4 v = src[i];
            __nv_bfloat16 h0, l0, h1, l1, h2, l2, h3, l3;
            split_bf16(v.x, h0, l0); split_bf16(v.y, h1, l1);
            split_bf16(v.z, h2, l2); split_bf16(v.w, h3, l3);
            *(uint2*)(Ah + i * 8) = make_uint2(pack2(h0, h1), pack2(h2, h3));
            *(uint2*)(Al + i * 8) = make_uint2(pack2(l0, l1), pack2(l2, l3));
        }
    }

    CPA_WAIT(0);
    __syncthreads();

    const uint32_t frag_off = (uint32_t)(l & 15) * 272u + (uint32_t)((l >> 4) << 3) * 2u;
    const uint32_t aAddrH = sb + SM_AH + frag_off + (uint32_t)wid * (16u * 272u);
    const uint32_t aAddrL = aAddrH + TILE_B;
    const uint32_t w1Addr = sb + SM_W1H + frag_off;
    const uint32_t w2Addr = sb + SM_W2H + frag_off;

    float c2[64];
    #pragma unroll
    for (int i = 0; i < 64; i++) c2[i] = 0.0f;

    uint32_t ha[32], la[32];

    #pragma unroll 1
    for (int h = 0; h < 2; h++) {
        // GEMM1 half
        float c1[64];
        #pragma unroll
        for (int i = 0; i < 64; i++) c1[i] = 0.0f;

        #pragma unroll 1
        for (int kc = 0; kc < 8; kc++) {
            uint32_t a0, a1, a2, a3, e0, e1, e2, e3;
            LDSM4(a0, a1, a2, a3, aAddrH + kc * 32);
            LDSM4(e0, e1, e2, e3, aAddrL + kc * 32);
            #pragma unroll
            for (int gi = 0; gi < 8; gi++) {
                uint32_t addr = w1Addr + (uint32_t)gi * (16u * 272u) + (uint32_t)kc * 32u;
                uint32_t b0, b1r, b2r, b3, u0, u1, u2, u3;
                LDSM4(b0, b1r, b2r, b3, addr);
                MMA_BF16(c1 + 8 * gi,     a0, a1, a2, a3, b0,  b2r);
                MMA_BF16(c1 + 8 * gi + 4, a0, a1, a2, a3, b1r, b3);
                LDSM4(u0, u1, u2, u3, addr + TILE_B);
                MMA_BF16(c1 + 8 * gi,     a0, a1, a2, a3, u0,  u2);
                MMA_BF16(c1 + 8 * gi + 4, a0, a1, a2, a3, u1,  u3);
                MMA_BF16(c1 + 8 * gi,     e0, e1, e2, e3, b0,  b2r);
                MMA_BF16(c1 + 8 * gi + 4, e0, e1, e2, e3, b1r, b3);
            }
        }

        __syncthreads();                   // all warps done reading W1[h]
        if (h == 0) {                      // prefetch W1 half 1 (group A)
            cpa_tile(sb + SM_W1H, glW1h + TILE_B, t);
            cpa_tile(sb + SM_W1L, glW1l + TILE_B, t);
            CPA_COMMIT();
        }

        // convert: relu(c1 + b1) -> bf16 hi/lo A-fragments
        #pragma unroll
        for (int j = 0; j < 16; j++) {
            int col = h * 128 + j * 8 + ((l & 3) << 1);
            float2 bb = *(const float2*)(b1 + col);
            float v0 = fmaxf(c1[4 * j + 0] + bb.x, 0.0f);
            float v1 = fmaxf(c1[4 * j + 1] + bb.y, 0.0f);
            float v2 = fmaxf(c1[4 * j + 2] + bb.x, 0.0f);
            float v3 = fmaxf(c1[4 * j + 3] + bb.y, 0.0f);
            __nv_bfloat16 h0, l0, h1, l1, h2, l2, h3, l3;
            split_bf16(v0, h0, l0); split_bf16(v1, h1, l1);
            split_bf16(v2, h2, l2); split_bf16(v3, h3, l3);
            ha[2 * j]     = pack2(h0, h1);
            la[2 * j]     = pack2(l0, l1);
            ha[2 * j + 1] = pack2(h2, h3);
            la[2 * j + 1] = pack2(l2, l3);
        }

        if (h == 1) {                      // W2 half 1 (group B) must be resident
            CPA_WAIT(0);
            __syncthreads();
        }

        // GEMM2 half (accumulate into c2)
        #pragma unroll 1
        for (int kc = 0; kc < 8; kc++) {
            uint32_t a0 = ha[4 * kc], a1 = ha[4 * kc + 1], a2 = ha[4 * kc + 2], a3 = ha[4 * kc + 3];
            uint32_t e0 = la[4 * kc], e1 = la[4 * kc + 1], e2 = la[4 * kc + 2], e3 = la[4 * kc + 3];
            #pragma unroll
            for (int gi = 0; gi < 8; gi++) {
                uint32_t addr = w2Addr + (uint32_t)gi * (16u * 272u) + (uint32_t)kc * 32u;
                uint32_t b0, b1r, b2r, b3, u0, u1, u2, u3;
                LDSM4(b0, b1r, b2r, b3, addr);
                MMA_BF16(c2 + 8 * gi,     a0, a1, a2, a3, b0,  b2r);
                MMA_BF16(c2 + 8 * gi + 4, a0, a1, a2, a3, b1r, b3);
                LDSM4(u0, u1, u2, u3, addr + TILE_B);
                MMA_BF16(c2 + 8 * gi,     a0, a1, a2, a3, u0,  u2);
                MMA_BF16(c2 + 8 * gi + 4, a0, a1, a2, a3, u1,  u3);
                MMA_BF16(c2 + 8 * gi,     e0, e1, e2, e3, b0,  b2r);
                MMA_BF16(c2 + 8 * gi + 4, e0, e1, e2, e3, b1r, b3);
            }
        }

        if (h == 0) {
            __syncthreads();               // all warps done reading W2[0]
            cpa_tile(sb + SM_W2H, glW2h + TILE_B, t);
            cpa_tile(sb + SM_W2L, glW2l + TILE_B, t);
            CPA_COMMIT();
            CPA_WAIT(1);                   // W1 half 1 complete
            __syncthreads();
        }
    }

    // epilogue: out = c2 + b2
    {
        const int mr = m0cta + wid * 16 + (l >> 2);
        #pragma unroll
        for (int j = 0; j < 16; j++) {
            int n0 = j * 8 + ((l & 3) << 1);
            int branch = n0 >> 6, f = n0 & 63;
            float2 bb = *(const float2*)(b2 + n0);
            #pragma unroll
            for (int rr = 0; rr < 2; rr++) {
                int m = mr + rr * 8;
                int p = m >> 15, e = m & (E_ - 1);
                size_t orow = (size_t)N0_ + ((size_t)p << 16) + 2u * (size_t)e + (size_t)branch;
                float2 v;
                v.x = c2[4 * j + 2 * rr + 0] + bb.x;
                v.y = c2[4 * j + 2 * rr + 1] + bb.y;
                *(float2*)(out + orow * 64 + f) = v;
            }
        }
    }
}

// ---------------- edge / attr / event fills ----------------
__global__ void copy_old_edges_kernel(const int* __restrict__ ei,
                                      const int* __restrict__ ea,
                                      float* __restrict__ out)
{
    int i = blockIdx.x * blockDim.x + threadIdx.x;
    if (i < NE_OLD_) {
        out[EI_OFF_ + i]                   = (float)ei[i];
        out[EI_OFF_ + (size_t)NE_TOT_ + i] = (float)ei[NE_OLD_ + i];
        out[EA_OFF_ + i]                   = (float)ea[i];
    }
}

__global__ void new_edges_kernel(float* __restrict__ out)
{
    int i = blockIdx.x * blockDim.x + threadIdx.x;
    if (i >= NE_NEW_) return;
    int p   = i >> 18;
    int rem = i & 262143;
    int dm1 = rem >> 16;
    int j   = rem & 65535;
    int e   = j & (E_ - 1);
    int anc = E_ * ((8 >> dm1) - 1);
    int src = anc + (p >> dm1) * E_ + e;
    int tgt = N0_ + (p << 16) + j;
    out[EI_OFF_ + NE_OLD_ + i]                   = (float)src;
    out[EI_OFF_ + (size_t)NE_TOT_ + NE_OLD_ + i] = (float)tgt;
    out[EA_OFF_ + NE_OLD_ + i]                   = (float)(dm1 + 1);
}

__global__ void event_kernel(const int* __restrict__ ev, float* __restrict__ out)
{
    int i = blockIdx.x * blockDim.x + threadIdx.x;
    if (i < NNODES_) {
        float v = (i < N0_) ? (float)ev[i] : (float)((i - N0_) & (E_ - 1));
        out[EV_OFF_ + i] = v;
    }
}

// ---------------- launch ----------------
extern "C" void kernel_launch(void* const* d_in, const int* in_sizes, int n_in,
                              void* d_out, int out_size)
{
    const float* x  = (const float*)d_in[0];
    const int*   ei = (const int*)  d_in[1];
    const int*   ea = (const int*)  d_in[2];
    const int*   ev = (const int*)  d_in[3];
    const float* g  = (const float*)d_in[4];
    const float* W1 = (const float*)d_in[5];
    const float* b1 = (const float*)d_in[6];
    const float* W2 = (const float*)d_in[7];
    const float* b2 = (const float*)d_in[8];
    float* out = (float*)d_out;

    cudaMemcpyAsync(out, x, (size_t)N0_ * 64 * sizeof(float),
                    cudaMemcpyDeviceToDevice);

    prep_w1_kernel<<<128, 256>>>(W1);
    prep_w2_kernel<<<128, 256>>>(W2);

    copy_old_edges_kernel<<<(NE_OLD_ + 255) / 256, 256>>>(ei, ea, out);
    new_edges_kernel<<<(NE_NEW_ + 255) / 256, 256>>>(out);
    event_kernel<<<(NNODES_ + 255) / 256, 256>>>(ev, out);

    cudaFuncSetAttribute(mlp_mma_kernel, cudaFuncAttributeMaxDynamicSharedMemorySize, SM_SZ);
    mlp_mma_kernel<<<MROWS_ / 128, 256, SM_SZ>>>(x, ev, g, b1, b2, out);
}

// round 4
// speedup vs baseline: 3.6295x; 1.3478x over previous
#include <cuda_runtime.h>
#include <cuda_fp16.h>
#include <cstdint>

// ---------------- problem constants ----------------
#define E_      32768
#define N0_     (15 * E_)
#define NTILES_ 2048                  // 262144 MLP rows / 128
#define NE_OLD_ 1114112
#define NE_NEW_ 2097152
#define NE_TOT_ (NE_OLD_ + NE_NEW_)
#define NNODES_ (31 * E_)

#define EI_OFF_ ((size_t)NNODES_ * 64)
#define EA_OFF_ (EI_OFF_ + 2ull * NE_TOT_)
#define EV_OFF_ (EA_OFF_ + (size_t)NE_TOT_)

// ---------------- smem layout (bytes) ----------------
#define TILE_B  34816                 // 128 rows x 272 B (136 fp16, padded)
#define SM_AH   0
#define SM_AL   (SM_AH + TILE_B)      // 34816
#define SM_W1   (SM_AL + TILE_B)      // 69632   : 2 tiles [h][128n][272B]
#define SM_W2   (SM_W1 + 2 * TILE_B)  // 139264  : 2 tiles [kh][128n][272B]
#define SM_B1   (SM_W2 + 2 * TILE_B)  // 208896  : 256 floats
#define SM_B2   (SM_B1 + 1024)        // 209920  : 128 floats
#define SM_SZ   (SM_B2 + 512)         // 210432

// ---------------- PTX helpers (base ISA only) ----------------
__device__ __forceinline__ uint32_t smem_u32(const void* p) {
    uint32_t a;
    asm("{ .reg .u64 t; cvta.to.shared.u64 t, %1; cvt.u32.u64 %0, t; }" : "=r"(a) : "l"(p));
    return a;
}

#define CPA16(dst, src) asm volatile("cp.async.cg.shared.global [%0], [%1], 16;" :: "r"(dst), "l"(src) : "memory")
#define CPA_COMMIT()    asm volatile("cp.async.commit_group;" ::: "memory")
#define CPA_WAIT(n)     asm volatile("cp.async.wait_group %0;" :: "n"(n) : "memory")

#define LDSM4(r0, r1, r2, r3, a)                                                   \
    asm volatile("ldmatrix.sync.aligned.m8n8.x4.shared.b16 {%0,%1,%2,%3}, [%4];"   \
        : "=r"(r0), "=r"(r1), "=r"(r2), "=r"(r3) : "r"(a))

#define MMA_F16(d, a0, a1, a2, a3, b0, b1)                                         \
    asm volatile("mma.sync.aligned.m16n8k16.row.col.f32.f16.f16.f32 "              \
        "{%0,%1,%2,%3}, {%4,%5,%6,%7}, {%8,%9}, {%0,%1,%2,%3};"                    \
        : "+f"((d)[0]), "+f"((d)[1]), "+f"((d)[2]), "+f"((d)[3])                   \
        : "r"(a0), "r"(a1), "r"(a2), "r"(a3), "r"(b0), "r"(b1))

__device__ __forceinline__ uint32_t pack2h(__half a, __half b) {
    return ((uint32_t)__half_as_ushort(b) << 16) | (uint32_t)__half_as_ushort(a);
}
__device__ __forceinline__ void split_h(float v, __half& h, __half& l) {
    h = __float2half(v);
    l = __float2half(v - __half2float(h));
}

// ---------------- pre-padded fp16 weight images + work ticket ----------------
__device__ __align__(16) unsigned char glW1[2 * TILE_B];  // [h][128n][272B]
__device__ __align__(16) unsigned char glW2[2 * TILE_B];  // [kh][128n][272B]
__device__ int g_ticket;

__global__ void prep_w1_kernel(const float* __restrict__ W1) {
    if (blockIdx.x == 0 && threadIdx.x == 0) g_ticket = 0;   // reset work queue
    int i = blockIdx.x * blockDim.x + threadIdx.x;
    if (i >= 256 * 128) return;
    int n = i >> 7, k = i & 127;
    uint32_t off = (uint32_t)(n >> 7) * TILE_B + (uint32_t)(n & 127) * 272u + (uint32_t)k * 2u;
    *(__half*)(glW1 + off) = __float2half(W1[k * 256 + n]);
}
__global__ void prep_w2_kernel(const float* __restrict__ W2) {
    int i = blockIdx.x * blockDim.x + threadIdx.x;
    if (i >= 128 * 256) return;
    int n = i >> 8, k = i & 255;
    uint32_t off = (uint32_t)(k >> 7) * TILE_B + (uint32_t)n * 272u + (uint32_t)(k & 127) * 2u;
    *(__half*)(glW2 + off) = __float2half(W2[k * 128 + n]);
}

// ---------------- persistent fused MLP (fp16 2-pass split-A) ----------------
__global__ void __launch_bounds__(256, 1)
mlp_mma_kernel(const float* __restrict__ x, const int* __restrict__ ev,
               const float* __restrict__ g,
               const float* __restrict__ b1, const float* __restrict__ b2,
               float* __restrict__ out)
{
    extern __shared__ __align__(128) unsigned char sm[];
    __shared__ int s_tile;

    const int t = threadIdx.x;
    const int wid = t >> 5, l = t & 31;
    const uint32_t sb = smem_u32(sm);

    // ---- all weights resident: 2x69632 bytes via cp.async ----
    for (int i = t; i < 4352; i += 256) {
        CPA16(sb + SM_W1 + (uint32_t)i * 16, glW1 + (size_t)i * 16);
        CPA16(sb + SM_W2 + (uint32_t)i * 16, glW2 + (size_t)i * 16);
    }
    CPA_COMMIT();

    // biases to smem
    ((float*)(sm + SM_B1))[t] = b1[t];
    if (t < 128) ((float*)(sm + SM_B2))[t] = b2[t];

    CPA_WAIT(0);
    __syncthreads();

    const uint32_t frag_off = (uint32_t)(l & 15) * 272u + (uint32_t)((l >> 4) << 4);
    const uint32_t aAddrH = sb + SM_AH + frag_off + (uint32_t)wid * (16u * 272u);
    const uint32_t aAddrL = aAddrH + TILE_B;
    const float* b1s = (const float*)(sm + SM_B1);
    const float* b2s = (const float*)(sm + SM_B2);

    while (true) {
        if (t == 0) s_tile = atomicAdd(&g_ticket, 1);
        __syncthreads();                       // publishes s_tile; also fences A reuse
        const int tile = s_tile;
        if (tile >= NTILES_) break;
        const int m0 = tile << 7;

        // ---- build A tile (fp16 hi/lo, padded rows) ----
        {
            const int r = t >> 1, half = t & 1;
            const int m = m0 + r;
            const float4* src;
            if (half == 0) src = (const float4*)(x + ((size_t)(7 * E_) + (size_t)m) * 64);
            else {
                const int e = ev[7 * E_ + m];
                src = (const float4*)(g + (size_t)e * 64);
            }
            unsigned char* Ah = sm + SM_AH + (size_t)r * 272 + (size_t)half * 128;
            unsigned char* Al = Ah + TILE_B;
            #pragma unroll
            for (int i = 0; i < 16; i++) {
                float4 v = src[i];
                __half h0, l0, h1, l1, h2, l2, h3, l3;
                split_h(v.x, h0, l0); split_h(v.y, h1, l1);
                split_h(v.z, h2, l2); split_h(v.w, h3, l3);
                *(uint2*)(Ah + i * 8) = make_uint2(pack2h(h0, h1), pack2h(h2, h3));
                *(uint2*)(Al + i * 8) = make_uint2(pack2h(l0, l1), pack2h(l2, l3));
            }
        }
        __syncthreads();

        float c2[64];
        #pragma unroll
        for (int i = 0; i < 64; i++) c2[i] = 0.0f;

        #pragma unroll 1
        for (int h = 0; h < 2; h++) {
            // ---- GEMM1 half h: c1 = A @ W1[:, h*128:+128] (2-pass hi/lo A) ----
            float c1[64];
            #pragma unroll
            for (int i = 0; i < 64; i++) c1[i] = 0.0f;

            const uint32_t w1Addr = sb + SM_W1 + (uint32_t)h * TILE_B + frag_off;
            #pragma unroll 1
            for (int kc = 0; kc < 8; kc++) {
                uint32_t a0, a1, a2, a3, e0, e1, e2, e3;
                LDSM4(a0, a1, a2, a3, aAddrH + kc * 32);
                LDSM4(e0, e1, e2, e3, aAddrL + kc * 32);
                #pragma unroll
                for (int gi = 0; gi < 8; gi++) {
                    uint32_t addr = w1Addr + (uint32_t)gi * (16u * 272u) + (uint32_t)kc * 32u;
                    uint32_t b0, b1r, b2r, b3;
                    LDSM4(b0, b1r, b2r, b3, addr);
                    MMA_F16(c1 + 8 * gi,     a0, a1, a2, a3, b0,  b2r);
                    MMA_F16(c1 + 8 * gi + 4, a0, a1, a2, a3, b1r, b3);
                    MMA_F16(c1 + 8 * gi,     e0, e1, e2, e3, b0,  b2r);
                    MMA_F16(c1 + 8 * gi + 4, e0, e1, e2, e3, b1r, b3);
                }
            }

            // ---- convert: relu(c1 + b1) -> fp16 hi/lo A-fragments ----
            uint32_t ha[32], la[32];
            #pragma unroll
            for (int j = 0; j < 16; j++) {
                int col = h * 128 + j * 8 + ((l & 3) << 1);
                float2 bb = *(const float2*)(b1s + col);
                float v0 = fmaxf(c1[4 * j + 0] + bb.x, 0.0f);
                float v1 = fmaxf(c1[4 * j + 1] + bb.y, 0.0f);
                float v2 = fmaxf(c1[4 * j + 2] + bb.x, 0.0f);
                float v3 = fmaxf(c1[4 * j + 3] + bb.y, 0.0f);
                __half h0, l0, h1, l1, h2, l2, h3, l3;
                split_h(v0, h0, l0); split_h(v1, h1, l1);
                split_h(v2, h2, l2); split_h(v3, h3, l3);
                ha[2 * j]     = pack2h(h0, h1);
                la[2 * j]     = pack2h(l0, l1);
                ha[2 * j + 1] = pack2h(h2, h3);
                la[2 * j + 1] = pack2h(l2, l3);
            }

            // ---- GEMM2 half h: c2 += H[:, h*128:+128] @ W2[h*128:+128, :] ----
            const uint32_t w2Addr = sb + SM_W2 + (uint32_t)h * TILE_B + frag_off;
            #pragma unroll 1
            for (int kc = 0; kc < 8; kc++) {
                uint32_t a0 = ha[4 * kc], a1 = ha[4 * kc + 1], a2 = ha[4 * kc + 2], a3 = ha[4 * kc + 3];
                uint32_t e0 = la[4 * kc], e1 = la[4 * kc + 1], e2 = la[4 * kc + 2], e3 = la[4 * kc + 3];
                #pragma unroll
                for (int gi = 0; gi < 8; gi++) {
                    uint32_t addr = w2Addr + (uint32_t)gi * (16u * 272u) + (uint32_t)kc * 32u;
                    uint32_t b0, b1r, b2r, b3;
                    LDSM4(b0, b1r, b2r, b3, addr);
                    MMA_F16(c2 + 8 * gi,     a0, a1, a2, a3, b0,  b2r);
                    MMA_F16(c2 + 8 * gi + 4, a0, a1, a2, a3, b1r, b3);
                    MMA_F16(c2 + 8 * gi,     e0, e1, e2, e3, b0,  b2r);
                    MMA_F16(c2 + 8 * gi + 4, e0, e1, e2, e3, b1r, b3);
                }
            }
        }

        // ---- epilogue: out = c2 + b2, scattered rows ----
        {
            const int mr = m0 + wid * 16 + (l >> 2);
            #pragma unroll
            for (int j = 0; j < 16; j++) {
                int n0 = j * 8 + ((l & 3) << 1);
                int branch = n0 >> 6, f = n0 & 63;
                float2 bb = *(const float2*)(b2s + n0);
                #pragma unroll
                for (int rr = 0; rr < 2; rr++) {
                    int m = mr + rr * 8;
                    int p = m >> 15, e = m & (E_ - 1);
                    size_t orow = (size_t)N0_ + ((size_t)p << 16) + 2u * (size_t)e + (size_t)branch;
                    float2 v;
                    v.x = c2[4 * j + 2 * rr + 0] + bb.x;
                    v.y = c2[4 * j + 2 * rr + 1] + bb.y;
                    *(float2*)(out + orow * 64 + f) = v;
                }
            }
        }
    }
}

// ---------------- edge / attr / event fills ----------------
__global__ void copy_old_edges_kernel(const int* __restrict__ ei,
                                      const int* __restrict__ ea,
                                      float* __restrict__ out)
{
    int i = blockIdx.x * blockDim.x + threadIdx.x;
    if (i < NE_OLD_) {
        out[EI_OFF_ + i]                   = (float)ei[i];
        out[EI_OFF_ + (size_t)NE_TOT_ + i] = (float)ei[NE_OLD_ + i];
        out[EA_OFF_ + i]                   = (float)ea[i];
    }
}

__global__ void new_edges_kernel(float* __restrict__ out)
{
    int i = blockIdx.x * blockDim.x + threadIdx.x;
    if (i >= NE_NEW_) return;
    int p   = i >> 18;
    int rem = i & 262143;
    int dm1 = rem >> 16;
    int j   = rem & 65535;
    int e   = j & (E_ - 1);
    int anc = E_ * ((8 >> dm1) - 1);
    int src = anc + (p >> dm1) * E_ + e;
    int tgt = N0_ + (p << 16) + j;
    out[EI_OFF_ + NE_OLD_ + i]                   = (float)src;
    out[EI_OFF_ + (size_t)NE_TOT_ + NE_OLD_ + i] = (float)tgt;
    out[EA_OFF_ + NE_OLD_ + i]                   = (float)(dm1 + 1);
}

__global__ void event_kernel(const int* __restrict__ ev, float* __restrict__ out)
{
    int i = blockIdx.x * blockDim.x + threadIdx.x;
    if (i < NNODES_) {
        float v = (i < N0_) ? (float)ev[i] : (float)((i - N0_) & (E_ - 1));
        out[EV_OFF_ + i] = v;
    }
}

// ---------------- launch ----------------
extern "C" void kernel_launch(void* const* d_in, const int* in_sizes, int n_in,
                              void* d_out, int out_size)
{
    const float* x  = (const float*)d_in[0];
    const int*   ei = (const int*)  d_in[1];
    const int*   ea = (const int*)  d_in[2];
    const int*   ev = (const int*)  d_in[3];
    const float* g  = (const float*)d_in[4];
    const float* W1 = (const float*)d_in[5];
    const float* b1 = (const float*)d_in[6];
    const float* W2 = (const float*)d_in[7];
    const float* b2 = (const float*)d_in[8];
    float* out = (float*)d_out;

    // lazily created side stream + events (host resources only; no device mem)
    static cudaStream_t s_side = nullptr;
    static cudaEvent_t ev_fork = nullptr, ev_join = nullptr;
    if (s_side == nullptr) {
        cudaStreamCreateWithFlags(&s_side, cudaStreamNonBlocking);
        cudaEventCreateWithFlags(&ev_fork, cudaEventDisableTiming);
        cudaEventCreateWithFlags(&ev_join, cudaEventDisableTiming);
    }

    // fork: copy + fills on side stream, concurrent with prep + MLP
    cudaEventRecord(ev_fork, 0);
    cudaStreamWaitEvent(s_side, ev_fork, 0);

    cudaMemcpyAsync(out, x, (size_t)N0_ * 64 * sizeof(float),
                    cudaMemcpyDeviceToDevice, s_side);
    copy_old_edges_kernel<<<(NE_OLD_ + 255) / 256, 256, 0, s_side>>>(ei, ea, out);
    new_edges_kernel<<<(NE_NEW_ + 255) / 256, 256, 0, s_side>>>(out);
    event_kernel<<<(NNODES_ + 255) / 256, 256, 0, s_side>>>(ev, out);
    cudaEventRecord(ev_join, s_side);

    // main stream: weight prep (+ ticket reset) then persistent MLP
    prep_w1_kernel<<<128, 256>>>(W1);
    prep_w2_kernel<<<128, 256>>>(W2);

    cudaFuncSetAttribute(mlp_mma_kernel, cudaFuncAttributeMaxDynamicSharedMemorySize, SM_SZ);
    mlp_mma_kernel<<<152, 256, SM_SZ>>>(x, ev, g, b1, b2, out);

    // join
    cudaStreamWaitEvent(0, ev_join, 0);
}

// round 5
// speedup vs baseline: 5.1200x; 1.4107x over previous
#include <cuda_runtime.h>
#include <cuda_fp16.h>
#include <cstdint>

// ---------------- problem constants ----------------
#define E_      32768
#define N0_     (15 * E_)
#define NTILES_ 2048                  // 262144 MLP rows / 128
#define NE_OLD_ 1114112
#define NE_NEW_ 2097152
#define NE_TOT_ (NE_OLD_ + NE_NEW_)
#define NNODES_ (31 * E_)

#define EI_OFF_ ((size_t)NNODES_ * 64)
#define EA_OFF_ (EI_OFF_ + 2ull * NE_TOT_)
#define EV_OFF_ (EA_OFF_ + (size_t)NE_TOT_)

// ---------------- smem layout (bytes) ----------------
#define TILE_B  34816                 // 128 rows x 272 B (136 fp16, padded)
#define SM_A0   0
#define SM_A1   (SM_A0 + TILE_B)      // 34816  (double-buffered A)
#define SM_W1   (SM_A1 + TILE_B)      // 69632  : 2 tiles [h][128n][272B]
#define SM_W2   (SM_W1 + 2 * TILE_B)  // 139264 : 2 tiles [kh][128n][272B]
#define SM_B1   (SM_W2 + 2 * TILE_B)  // 208896 : 256 floats
#define SM_B2   (SM_B1 + 1024)        // 209920 : 128 floats
#define SM_SZ   (SM_B2 + 512)         // 210432

// ---------------- PTX helpers (base ISA only) ----------------
__device__ __forceinline__ uint32_t smem_u32(const void* p) {
    uint32_t a;
    asm("{ .reg .u64 t; cvta.to.shared.u64 t, %1; cvt.u32.u64 %0, t; }" : "=r"(a) : "l"(p));
    return a;
}

#define CPA16(dst, src) asm volatile("cp.async.cg.shared.global [%0], [%1], 16;" :: "r"(dst), "l"(src) : "memory")
#define CPA_COMMIT()    asm volatile("cp.async.commit_group;" ::: "memory")
#define CPA_WAIT(n)     asm volatile("cp.async.wait_group %0;" :: "n"(n) : "memory")

#define LDSM4(r0, r1, r2, r3, a)                                                   \
    asm volatile("ldmatrix.sync.aligned.m8n8.x4.shared.b16 {%0,%1,%2,%3}, [%4];"   \
        : "=r"(r0), "=r"(r1), "=r"(r2), "=r"(r3) : "r"(a))

#define MMA_F16(d, a0, a1, a2, a3, b0, b1)                                         \
    asm volatile("mma.sync.aligned.m16n8k16.row.col.f32.f16.f16.f32 "              \
        "{%0,%1,%2,%3}, {%4,%5,%6,%7}, {%8,%9}, {%0,%1,%2,%3};"                    \
        : "+f"((d)[0]), "+f"((d)[1]), "+f"((d)[2]), "+f"((d)[3])                   \
        : "r"(a0), "r"(a1), "r"(a2), "r"(a3), "r"(b0), "r"(b1))

__device__ __forceinline__ uint32_t h2u(__half2 h) {
    return *reinterpret_cast<uint32_t*>(&h);
}

// ---------------- pre-padded fp16 weight images + work ticket ----------------
__device__ __align__(16) unsigned char glW1[2 * TILE_B];  // [h][128n][272B]
__device__ __align__(16) unsigned char glW2[2 * TILE_B];  // [kh][128n][272B]
__device__ int g_ticket;

__global__ void prep_w1_kernel(const float* __restrict__ W1) {
    if (blockIdx.x == 0 && threadIdx.x == 0) g_ticket = 0;   // reset work queue
    int i = blockIdx.x * blockDim.x + threadIdx.x;
    if (i >= 256 * 128) return;
    int n = i >> 7, k = i & 127;
    uint32_t off = (uint32_t)(n >> 7) * TILE_B + (uint32_t)(n & 127) * 272u + (uint32_t)k * 2u;
    *(__half*)(glW1 + off) = __float2half(W1[k * 256 + n]);
}
__global__ void prep_w2_kernel(const float* __restrict__ W2) {
    int i = blockIdx.x * blockDim.x + threadIdx.x;
    if (i >= 128 * 256) return;
    int n = i >> 8, k = i & 255;
    uint32_t off = (uint32_t)(k >> 7) * TILE_B + (uint32_t)n * 272u + (uint32_t)(k & 127) * 2u;
    *(__half*)(glW2 + off) = __float2half(W2[k * 128 + n]);
}

// build one 128-row A tile (fp16, padded rows) into smem buffer
__device__ __forceinline__ void build_A(unsigned char* Abuf, int m0,
                                        const float* __restrict__ x,
                                        const int* __restrict__ ev,
                                        const float* __restrict__ g, int t)
{
    const int r = t >> 1, half = t & 1;
    const int m = m0 + r;
    const float4* src;
    if (half == 0) src = (const float4*)(x + ((size_t)(7 * E_) + (size_t)m) * 64);
    else {
        const int e = ev[7 * E_ + m];
        src = (const float4*)(g + (size_t)e * 64);
    }
    unsigned char* Ah = Abuf + (size_t)r * 272 + (size_t)half * 128;
    #pragma unroll
    for (int i = 0; i < 16; i++) {
        float4 v = src[i];
        uint32_t u0 = h2u(__float22half2_rn(make_float2(v.x, v.y)));
        uint32_t u1 = h2u(__float22half2_rn(make_float2(v.z, v.w)));
        *(uint2*)(Ah + i * 8) = make_uint2(u0, u1);
    }
}

// ---------------- persistent fused MLP (fp16 single-pass, dbl-buffered A) ----------------
__global__ void __launch_bounds__(256, 1)
mlp_mma_kernel(const float* __restrict__ x, const int* __restrict__ ev,
               const float* __restrict__ g,
               const float* __restrict__ b1, const float* __restrict__ b2,
               float* __restrict__ out)
{
    extern __shared__ __align__(128) unsigned char sm[];
    __shared__ int s_tile[2];

    const int t = threadIdx.x;
    const int wid = t >> 5, l = t & 31;
    const uint32_t sb = smem_u32(sm);

    // ---- all weights resident: 2x69632 bytes via cp.async ----
    for (int i = t; i < 4352; i += 256) {
        CPA16(sb + SM_W1 + (uint32_t)i * 16, glW1 + (size_t)i * 16);
        CPA16(sb + SM_W2 + (uint32_t)i * 16, glW2 + (size_t)i * 16);
    }
    CPA_COMMIT();

    ((float*)(sm + SM_B1))[t] = b1[t];
    if (t < 128) ((float*)(sm + SM_B2))[t] = b2[t];

    const uint32_t frag_off = (uint32_t)(l & 15) * 272u + (uint32_t)((l >> 4) << 4);
    const float* b1s = (const float*)(sm + SM_B1);
    const float* b2s = (const float*)(sm + SM_B2);

    // ---- prologue: first ticket + first A build ----
    if (t == 0) s_tile[0] = atomicAdd(&g_ticket, 1);
    __syncthreads();                               // publishes s_tile[0]; weights may still be in flight
    int tile = s_tile[0];
    int cur = 0;
    if (tile < NTILES_) build_A(sm + SM_A0, tile << 7, x, ev, g, t);
    CPA_WAIT(0);                                   // weights resident

    while (tile < NTILES_) {
        if (t == 0) s_tile[cur ^ 1] = atomicAdd(&g_ticket, 1);
        __syncthreads();                           // A(cur) visible; next ticket published
        const int next = s_tile[cur ^ 1];
        const int m0 = tile << 7;

        const uint32_t aAddr = sb + (cur ? SM_A1 : SM_A0) + frag_off + (uint32_t)wid * (16u * 272u);

        float c2[64];
        #pragma unroll
        for (int i = 0; i < 64; i++) c2[i] = 0.0f;

        #pragma unroll 1
        for (int h = 0; h < 2; h++) {
            // ---- GEMM1 half h ----
            float c1[64];
            #pragma unroll
            for (int i = 0; i < 64; i++) c1[i] = 0.0f;

            const uint32_t w1Addr = sb + SM_W1 + (uint32_t)h * TILE_B + frag_off;
            #pragma unroll 1
            for (int kc = 0; kc < 8; kc++) {
                uint32_t a0, a1, a2, a3;
                LDSM4(a0, a1, a2, a3, aAddr + kc * 32);
                #pragma unroll
                for (int gi = 0; gi < 8; gi++) {
                    uint32_t addr = w1Addr + (uint32_t)gi * (16u * 272u) + (uint32_t)kc * 32u;
                    uint32_t b0, b1r, b2r, b3;
                    LDSM4(b0, b1r, b2r, b3, addr);
                    MMA_F16(c1 + 8 * gi,     a0, a1, a2, a3, b0,  b2r);
                    MMA_F16(c1 + 8 * gi + 4, a0, a1, a2, a3, b1r, b3);
                }
            }

            // ---- convert: relu(c1 + b1) -> fp16 A-fragments (packed cvt) ----
            uint32_t ha[32];
            #pragma unroll
            for (int j = 0; j < 16; j++) {
                int col = h * 128 + j * 8 + ((l & 3) << 1);
                float2 bb = *(const float2*)(b1s + col);
                float v0 = fmaxf(c1[4 * j + 0] + bb.x, 0.0f);
                float v1 = fmaxf(c1[4 * j + 1] + bb.y, 0.0f);
                float v2 = fmaxf(c1[4 * j + 2] + bb.x, 0.0f);
                float v3 = fmaxf(c1[4 * j + 3] + bb.y, 0.0f);
                ha[2 * j]     = h2u(__float22half2_rn(make_float2(v0, v1)));
                ha[2 * j + 1] = h2u(__float22half2_rn(make_float2(v2, v3)));
            }

            // hoist next-tile A build under first GEMM2 half
            if (h == 0 && next < NTILES_)
                build_A(sm + (cur ? SM_A0 : SM_A1), next << 7, x, ev, g, t);

            // ---- GEMM2 half h ----
            const uint32_t w2Addr = sb + SM_W2 + (uint32_t)h * TILE_B + frag_off;
            #pragma unroll 1
            for (int kc = 0; kc < 8; kc++) {
                uint32_t a0 = ha[4 * kc], a1 = ha[4 * kc + 1], a2 = ha[4 * kc + 2], a3 = ha[4 * kc + 3];
                #pragma unroll
                for (int gi = 0; gi < 8; gi++) {
                    uint32_t addr = w2Addr + (uint32_t)gi * (16u * 272u) + (uint32_t)kc * 32u;
                    uint32_t b0, b1r, b2r, b3;
                    LDSM4(b0, b1r, b2r, b3, addr);
                    MMA_F16(c2 + 8 * gi,     a0, a1, a2, a3, b0,  b2r);
                    MMA_F16(c2 + 8 * gi + 4, a0, a1, a2, a3, b1r, b3);
                }
            }
        }

        // ---- epilogue: out = c2 + b2, scattered rows ----
        {
            const int mr = m0 + wid * 16 + (l >> 2);
            #pragma unroll
            for (int j = 0; j < 16; j++) {
                int n0 = j * 8 + ((l & 3) << 1);
                int branch = n0 >> 6, f = n0 & 63;
                float2 bb = *(const float2*)(b2s + n0);
                #pragma unroll
                for (int rr = 0; rr < 2; rr++) {
                    int m = mr + rr * 8;
                    int p = m >> 15, e = m & (E_ - 1);
                    size_t orow = (size_t)N0_ + ((size_t)p << 16) + 2u * (size_t)e + (size_t)branch;
                    float2 v;
                    v.x = c2[4 * j + 2 * rr + 0] + bb.x;
                    v.y = c2[4 * j + 2 * rr + 1] + bb.y;
                    *(float2*)(out + orow * 64 + f) = v;
                }
            }
        }

        tile = next;
        cur ^= 1;
    }
}

// ---------------- edge / attr / event fills ----------------
__global__ void copy_old_edges_kernel(const int* __restrict__ ei,
                                      const int* __restrict__ ea,
                                      float* __restrict__ out)
{
    int i = blockIdx.x * blockDim.x + threadIdx.x;
    if (i < NE_OLD_) {
        out[EI_OFF_ + i]                   = (float)ei[i];
        out[EI_OFF_ + (size_t)NE_TOT_ + i] = (float)ei[NE_OLD_ + i];
        out[EA_OFF_ + i]                   = (float)ea[i];
    }
}

__global__ void new_edges_kernel(float* __restrict__ out)
{
    int i = blockIdx.x * blockDim.x + threadIdx.x;
    if (i >= NE_NEW_) return;
    int p   = i >> 18;
    int rem = i & 262143;
    int dm1 = rem >> 16;
    int j   = rem & 65535;
    int e   = j & (E_ - 1);
    int anc = E_ * ((8 >> dm1) - 1);
    int src = anc + (p >> dm1) * E_ + e;
    int tgt = N0_ + (p << 16) + j;
    out[EI_OFF_ + NE_OLD_ + i]                   = (float)src;
    out[EI_OFF_ + (size_t)NE_TOT_ + NE_OLD_ + i] = (float)tgt;
    out[EA_OFF_ + NE_OLD_ + i]                   = (float)(dm1 + 1);
}

__global__ void event_kernel(const int* __restrict__ ev, float* __restrict__ out)
{
    int i = blockIdx.x * blockDim.x + threadIdx.x;
    if (i < NNODES_) {
        float v = (i < N0_) ? (float)ev[i] : (float)((i - N0_) & (E_ - 1));
        out[EV_OFF_ + i] = v;
    }
}

// ---------------- launch ----------------
extern "C" void kernel_launch(void* const* d_in, const int* in_sizes, int n_in,
                              void* d_out, int out_size)
{
    const float* x  = (const float*)d_in[0];
    const int*   ei = (const int*)  d_in[1];
    const int*   ea = (const int*)  d_in[2];
    const int*   ev = (const int*)  d_in[3];
    const float* g  = (const float*)d_in[4];
    const float* W1 = (const float*)d_in[5];
    const float* b1 = (const float*)d_in[6];
    const float* W2 = (const float*)d_in[7];
    const float* b2 = (const float*)d_in[8];
    float* out = (float*)d_out;

    static cudaStream_t s_side = nullptr;
    static cudaEvent_t ev_fork = nullptr, ev_join = nullptr;
    if (s_side == nullptr) {
        cudaStreamCreateWithFlags(&s_side, cudaStreamNonBlocking);
        cudaEventCreateWithFlags(&ev_fork, cudaEventDisableTiming);
        cudaEventCreateWithFlags(&ev_join, cudaEventDisableTiming);
    }

    // fork: copy + fills on side stream, concurrent with prep + MLP
    cudaEventRecord(ev_fork, 0);
    cudaStreamWaitEvent(s_side, ev_fork, 0);

    cudaMemcpyAsync(out, x, (size_t)N0_ * 64 * sizeof(float),
                    cudaMemcpyDeviceToDevice, s_side);
    copy_old_edges_kernel<<<(NE_OLD_ + 255) / 256, 256, 0, s_side>>>(ei, ea, out);
    new_edges_kernel<<<(NE_NEW_ + 255) / 256, 256, 0, s_side>>>(out);
    event_kernel<<<(NNODES_ + 255) / 256, 256, 0, s_side>>>(ev, out);
    cudaEventRecord(ev_join, s_side);

    // main stream: weight prep (+ ticket reset) then persistent MLP
    prep_w1_kernel<<<128, 256>>>(W1);
    prep_w2_kernel<<<128, 256>>>(W2);

    cudaFuncSetAttribute(mlp_mma_kernel, cudaFuncAttributeMaxDynamicSharedMemorySize, SM_SZ);
    mlp_mma_kernel<<<152, 256, SM_SZ>>>(x, ev, g, b1, b2, out);

    // join
    cudaStreamWaitEvent(0, ev_join, 0);
}